// round 1
// baseline (speedup 1.0000x reference)
#include <cuda_runtime.h>
#include <cuda_bf16.h>
#include <math.h>

// Problem constants (fixed by the dataset)
#define HID   1024
#define N1C   28
#define N2C   280
#define N3C   2800
#define BMAX  4096

// Scratch (allocation-free: __device__ globals)
__device__ float g_z1[BMAX * N1C];
__device__ float g_z2[BMAX * N2C];
__device__ float g_z3[BMAX * N3C];      // fallback if d_out can't hold logits3
__device__ float g_lossrows[BMAX];

// ---------------------------------------------------------------------------
// SGEMM:  Z[r, c] = sigmoid( sum_k X[r,k] * W[c,k] + bias[c] )
// X: [B, H] row-major, W: [N, H] row-major (so this is X @ W^T)
// Tile: BM=128, BN=128, BK=8, thread tile 8x8, 256 threads.
// ---------------------------------------------------------------------------
#define BM 128
#define BN 128
#define BK 8
#define TM 8
#define TN 8

__global__ __launch_bounds__(256)
void gemm_sigmoid_kernel(const float* __restrict__ X,
                         const float* __restrict__ W,
                         const float* __restrict__ bias,
                         float* __restrict__ Z,
                         int N, int H)
{
    __shared__ float As[BK][BM];
    __shared__ float Ws[BK][BN];

    const int tid  = threadIdx.x;
    const int brow = blockIdx.y;      // row tile of X
    const int bcol = blockIdx.x;      // col tile (rows of W)

    const int ty = tid / 16;          // 0..15 -> output rows
    const int tx = tid % 16;          // 0..15 -> output cols

    // loader mapping: 128 rows x 8 cols, one float4 per thread
    const int ldRow = tid >> 1;          // 0..127
    const int ldCol = (tid & 1) * 4;     // 0 or 4

    const float* Xp = X + (size_t)(brow * BM) * H;

    float acc[TM][TN];
#pragma unroll
    for (int i = 0; i < TM; i++)
#pragma unroll
        for (int j = 0; j < TN; j++) acc[i][j] = 0.0f;

    const int wRow = bcol * BN + ldRow;
    const bool wValid = (wRow < N);
    const float* Wp = W + (size_t)wRow * H;

    for (int k0 = 0; k0 < H; k0 += BK) {
        // load X tile (always in-bounds: B % 128 == 0, H % 8 == 0)
        float4 av = *(const float4*)(Xp + (size_t)ldRow * H + k0 + ldCol);
        As[ldCol + 0][ldRow] = av.x;
        As[ldCol + 1][ldRow] = av.y;
        As[ldCol + 2][ldRow] = av.z;
        As[ldCol + 3][ldRow] = av.w;

        float4 wv = make_float4(0.f, 0.f, 0.f, 0.f);
        if (wValid) wv = *(const float4*)(Wp + k0 + ldCol);
        Ws[ldCol + 0][ldRow] = wv.x;
        Ws[ldCol + 1][ldRow] = wv.y;
        Ws[ldCol + 2][ldRow] = wv.z;
        Ws[ldCol + 3][ldRow] = wv.w;

        __syncthreads();

#pragma unroll
        for (int k = 0; k < BK; k++) {
            float aR[TM], bR[TN];
            // vectorized smem reads
            float4 a0 = *(const float4*)&As[k][ty * TM + 0];
            float4 a1 = *(const float4*)&As[k][ty * TM + 4];
            aR[0]=a0.x; aR[1]=a0.y; aR[2]=a0.z; aR[3]=a0.w;
            aR[4]=a1.x; aR[5]=a1.y; aR[6]=a1.z; aR[7]=a1.w;
            float4 b0 = *(const float4*)&Ws[k][tx * TN + 0];
            float4 b1 = *(const float4*)&Ws[k][tx * TN + 4];
            bR[0]=b0.x; bR[1]=b0.y; bR[2]=b0.z; bR[3]=b0.w;
            bR[4]=b1.x; bR[5]=b1.y; bR[6]=b1.z; bR[7]=b1.w;
#pragma unroll
            for (int i = 0; i < TM; i++)
#pragma unroll
                for (int j = 0; j < TN; j++)
                    acc[i][j] = fmaf(aR[i], bR[j], acc[i][j]);
        }
        __syncthreads();
    }

    // epilogue: bias + sigmoid, guarded column writes
#pragma unroll
    for (int j = 0; j < TN; j++) {
        int c = bcol * BN + tx * TN + j;
        if (c >= N) continue;
        float bv = bias[c];
#pragma unroll
        for (int i = 0; i < TM; i++) {
            int r = brow * BM + ty * TM + i;
            float v = acc[i][j] + bv;
            Z[(size_t)r * N + c] = 1.0f / (1.0f + expf(-v));
        }
    }
}

// ---------------------------------------------------------------------------
// Epilogue: per-row logits + CE losses. One block (256 thr) per batch row.
// outZ initially holds z3 [B, 2800]; transformed in place to logits3.
// ---------------------------------------------------------------------------
__device__ __forceinline__ float blockMax(float v, float* red) {
    int t = threadIdx.x;
    red[t] = v; __syncthreads();
    for (int s = 128; s > 0; s >>= 1) {
        if (t < s) red[t] = fmaxf(red[t], red[t + s]);
        __syncthreads();
    }
    float r = red[0]; __syncthreads();
    return r;
}
__device__ __forceinline__ float blockSum(float v, float* red) {
    int t = threadIdx.x;
    red[t] = v; __syncthreads();
    for (int s = 128; s > 0; s >>= 1) {
        if (t < s) red[t] += red[t + s];
        __syncthreads();
    }
    float r = red[0]; __syncthreads();
    return r;
}

__global__ __launch_bounds__(256)
void epilogue_kernel(const float* __restrict__ z1,
                     const float* __restrict__ z2,
                     const int*   __restrict__ labels,
                     float* outZ,
                     float* __restrict__ loss_rows)
{
    __shared__ float s1[N1C];
    __shared__ float s2[N2C];
    __shared__ float s3[N2C];     // first 280 cols of z3 (all ancestors)
    __shared__ float red[256];
    __shared__ float slab;

    const int b = blockIdx.x;
    const int t = threadIdx.x;
    const int lab  = labels[b];
    const int lab1 = lab / 100;
    const int lab2 = lab / 10;

    float* orow = outZ + (size_t)b * N3C;

    for (int i = t; i < N1C; i += 256) s1[i] = z1[(size_t)b * N1C + i];
    for (int i = t; i < N2C; i += 256) s2[i] = z2[(size_t)b * N2C + i];
    for (int i = t; i < N2C; i += 256) s3[i] = orow[i];
    __syncthreads();

    // ---- level 1: logits = z1 ----
    float lmax = -1e30f;
    for (int k = t; k < N1C; k += 256) lmax = fmaxf(lmax, s1[k]);
    float m1 = blockMax(lmax, red);
    float lsum = 0.f;
    for (int k = t; k < N1C; k += 256) lsum += expf(s1[k] - m1);
    float sum1 = blockSum(lsum, red);
    float loss1 = logf(sum1) + m1 - s1[lab1];

    // ---- level 2: logits[k] = z2[k/10] * z2[k] ----
    lmax = -1e30f;
    for (int k = t; k < N2C; k += 256) lmax = fmaxf(lmax, s2[k / 10] * s2[k]);
    float m2 = blockMax(lmax, red);
    lsum = 0.f;
    for (int k = t; k < N2C; k += 256) lsum += expf(s2[k / 10] * s2[k] - m2);
    float sum2 = blockSum(lsum, red);
    float loss2 = logf(sum2) + m2 - s2[lab2 / 10] * s2[lab2];

    // ---- level 3: logits[k] = z3[k/100] * z3[k/10] * z3[k], in place ----
    lmax = -1e30f;
    for (int k = t; k < N3C; k += 256) {
        float z = (k < N2C) ? s3[k] : orow[k];
        float l = s3[k / 100] * s3[k / 10] * z;
        orow[k] = l;
        if (k == lab) slab = l;
        lmax = fmaxf(lmax, l);
    }
    float m3 = blockMax(lmax, red);   // includes __syncthreads (global writes visible)
    lsum = 0.f;
    for (int k = t; k < N3C; k += 256) lsum += expf(orow[k] - m3);
    float sum3 = blockSum(lsum, red);
    float loss3 = logf(sum3) + m3 - slab;

    if (t == 0) loss_rows[b] = loss1 + loss2 + loss3;
}

// ---------------------------------------------------------------------------
// Final deterministic loss reduction
// ---------------------------------------------------------------------------
__global__ __launch_bounds__(256)
void loss_reduce_kernel(const float* __restrict__ lr, float* __restrict__ dst, int B)
{
    __shared__ float red[256];
    int t = threadIdx.x;
    float s = 0.f;
    for (int i = t; i < B; i += 256) s += lr[i];
    red[t] = s; __syncthreads();
    for (int k = 128; k > 0; k >>= 1) {
        if (t < k) red[t] += red[t + k];
        __syncthreads();
    }
    if (t == 0) *dst = red[0] / (float)B;
}

// ---------------------------------------------------------------------------
extern "C" void kernel_launch(void* const* d_in, const int* in_sizes, int n_in,
                              void* d_out, int out_size)
{
    const float* x      = (const float*)d_in[0];
    const int*   labels = (const int*)  d_in[1];
    const float* W1     = (const float*)d_in[2];
    const float* b1     = (const float*)d_in[3];
    const float* W2     = (const float*)d_in[4];
    const float* b2     = (const float*)d_in[5];
    const float* W3     = (const float*)d_in[6];
    const float* b3     = (const float*)d_in[7];

    const int H = HID;
    int B = in_sizes[0] / H;
    if (B > BMAX) B = BMAX;

    float* out = (float*)d_out;

    float *z1p, *z2p, *z3p, *lrp;
    cudaGetSymbolAddress((void**)&z1p, g_z1);
    cudaGetSymbolAddress((void**)&z2p, g_z2);
    cudaGetSymbolAddress((void**)&z3p, g_z3);
    cudaGetSymbolAddress((void**)&lrp, g_lossrows);

    const size_t LE = (size_t)B * N3C;   // logits3 element count
    float* zdst = ((size_t)out_size >= LE) ? out : z3p;

    dim3 blk(256);
    gemm_sigmoid_kernel<<<dim3((N1C + BN - 1) / BN, B / BM), blk>>>(x, W1, b1, z1p, N1C, H);
    gemm_sigmoid_kernel<<<dim3((N2C + BN - 1) / BN, B / BM), blk>>>(x, W2, b2, z2p, N2C, H);
    gemm_sigmoid_kernel<<<dim3((N3C + BN - 1) / BN, B / BM), blk>>>(x, W3, b3, zdst, N3C, H);

    epilogue_kernel<<<B, 256>>>(z1p, z2p, labels, zdst, lrp);

    if ((size_t)out_size > LE) {
        loss_reduce_kernel<<<1, 256>>>(lrp, out + LE, B);
    } else if ((size_t)out_size < LE && out_size >= 1) {
        // output holds only the loss scalar
        loss_reduce_kernel<<<1, 256>>>(lrp, out, B);
    }
}

// round 3
// speedup vs baseline: 3.1905x; 3.1905x over previous
#include <cuda_runtime.h>
#include <cuda_bf16.h>
#include <math.h>
#include <stdint.h>

// Problem constants
#define HID   1024
#define KCAT  3072            // 3 * HID (hi*hi + hi*lo + lo*hi concatenation)
#define N1C   28
#define N2C   280
#define N3C   2800
#define BMAX  4096
// per-level N padded to 128-col tiles
#define N1P   128
#define N2P   384
#define N3P   2816
#define NT_COL 26             // 1 + 3 + 22 column tiles

#define BK    64              // bf16 per K-chunk (128 bytes/row)
#define NCHNK (KCAT / BK)     // 48

// ---------------------------------------------------------------------------
// Scratch (__device__ globals; allocation-free)
// ---------------------------------------------------------------------------
__device__ float g_z1[BMAX * N1C];
__device__ float g_z2[BMAX * N2C];
__device__ float g_z3[BMAX * N3C];
__device__ float g_lossrows[BMAX];

__device__ alignas(256) __nv_bfloat16 g_xc [BMAX * KCAT];   // [hi | hi | lo]
__device__ alignas(256) __nv_bfloat16 g_w1c[N1P  * KCAT];   // [hi | lo | hi]
__device__ alignas(256) __nv_bfloat16 g_w2c[N2P  * KCAT];
__device__ alignas(256) __nv_bfloat16 g_w3c[N3P  * KCAT];

// ---------------------------------------------------------------------------
// helpers
// ---------------------------------------------------------------------------
__device__ __forceinline__ uint32_t smem_u32(const void* p) {
    uint32_t a;
    asm("{ .reg .u64 t; cvta.to.shared.u64 t, %1; cvt.u32.u64 %0, t; }" : "=r"(a) : "l"(p));
    return a;
}
#define SWZ(off) ((off) ^ (((off) >> 3) & 0x70))

#define CP16(dst, src) \
    asm volatile("cp.async.cg.shared.global [%0], [%1], 16;" :: "r"(dst), "l"(src))
#define CP_COMMIT() asm volatile("cp.async.commit_group;" ::: "memory")
#define CP_WAIT(n)  asm volatile("cp.async.wait_group %0;" :: "n"(n) : "memory")

#define LDSM4(r0, r1, r2, r3, addr) \
    asm volatile("ldmatrix.sync.aligned.m8n8.x4.shared.b16 {%0,%1,%2,%3}, [%4];" \
                 : "=r"(r0), "=r"(r1), "=r"(r2), "=r"(r3) : "r"(addr))

#define MMA16816(d, a, b) \
    asm volatile("mma.sync.aligned.m16n8k16.row.col.f32.bf16.bf16.f32 " \
                 "{%0,%1,%2,%3}, {%4,%5,%6,%7}, {%8,%9}, {%0,%1,%2,%3};" \
                 : "+f"((d)[0]), "+f"((d)[1]), "+f"((d)[2]), "+f"((d)[3]) \
                 : "r"((a)[0]), "r"((a)[1]), "r"((a)[2]), "r"((a)[3]), \
                   "r"((b)[0]), "r"((b)[1]))

// ---------------------------------------------------------------------------
// fp32 [rows_valid, 1024] -> bf16 [rows_total, 3072] concatenated hi/lo split.
// slot s in {0,1,2}: value = (s == lo_slot) ? lo : hi.  Rows >= rows_valid -> 0.
// ---------------------------------------------------------------------------
__global__ __launch_bounds__(256)
void convert_cat_kernel(const float* __restrict__ src,
                        __nv_bfloat16* __restrict__ dst,
                        int rows_valid, int rows_total, int lo_slot)
{
    int i = blockIdx.x * blockDim.x + threadIdx.x;       // one per 4 elems
    int total = rows_total * (HID / 4);
    if (i >= total) return;
    int row = i / (HID / 4);
    int k4  = (i % (HID / 4)) * 4;

    float4 v = make_float4(0.f, 0.f, 0.f, 0.f);
    if (row < rows_valid) v = *(const float4*)(src + (size_t)row * HID + k4);

    __nv_bfloat16 h[4], l[4];
    float vv[4] = {v.x, v.y, v.z, v.w};
#pragma unroll
    for (int t = 0; t < 4; t++) {
        h[t] = __float2bfloat16(vv[t]);
        l[t] = __float2bfloat16(vv[t] - __bfloat162float(h[t]));
    }
    __nv_bfloat162 hp0{h[0], h[1]}, hp1{h[2], h[3]};
    __nv_bfloat162 lp0{l[0], l[1]}, lp1{l[2], l[3]};

    size_t base = (size_t)row * KCAT + k4;
#pragma unroll
    for (int s = 0; s < 3; s++) {
        __nv_bfloat162* d2 = (__nv_bfloat162*)(dst + base + (size_t)s * HID);
        if (s == lo_slot) { d2[0] = lp0; d2[1] = lp1; }
        else              { d2[0] = hp0; d2[1] = hp1; }
    }
}

// ---------------------------------------------------------------------------
// Fused bf16 mma.sync GEMM: Z = sigmoid(X' @ W'^T + b), K = 3072.
// CTA tile 128x128, K-chunk 64, 3-stage cp.async, 8 warps (warp tile 32x64).
// grid = (26, B/128), block = 256.
// ---------------------------------------------------------------------------
#define STAGE_SZ 32768u        // A tile 16KB + B tile 16KB
#define SMEM_BYTES (1024u + 3u * STAGE_SZ)

__global__ __launch_bounds__(256)
void gemm_mma_kernel(const __nv_bfloat16* __restrict__ xc,
                     const __nv_bfloat16* __restrict__ w1c, const float* __restrict__ b1, float* __restrict__ z1,
                     const __nv_bfloat16* __restrict__ w2c, const float* __restrict__ b2, float* __restrict__ z2,
                     const __nv_bfloat16* __restrict__ w3c, const float* __restrict__ b3, float* __restrict__ z3)
{
    extern __shared__ char smem[];
    const uint32_t sb = (smem_u32(smem) + 1023u) & ~1023u;

    const int tid  = threadIdx.x;
    const int lane = tid & 31;
    const int w    = tid >> 5;
    const int brow = blockIdx.y;
    const int bcol = blockIdx.x;

    const __nv_bfloat16* wc; const float* bias; float* Z; int N, lcol;
    if (bcol == 0)      { wc = w1c; bias = b1; Z = z1; N = N1C; lcol = 0; }
    else if (bcol <= 3) { wc = w2c; bias = b2; Z = z2; N = N2C; lcol = bcol - 1; }
    else                { wc = w3c; bias = b3; Z = z3; N = N3C; lcol = bcol - 4; }

    const int m0 = brow * 128;
    const int n0 = lcol * 128;

    const char* Abase = (const char*)(xc + (size_t)m0 * KCAT);
    const char* Bbase = (const char*)(wc + (size_t)n0 * KCAT);

    // ---- cp.async loader: 2048 x 16B per stage (A first 1024, B next 1024) ----
    auto issue_loads = [&](int c, int s) {
        const uint32_t st = sb + (uint32_t)s * STAGE_SZ;
        const int coff = c * 128;                        // byte offset along K
#pragma unroll
        for (int it = 0; it < 8; it++) {
            int i = tid + it * 256;                      // 0..2047
            int isB = (i >= 1024);
            int idx = i & 1023;
            int row = idx >> 3;                          // 0..127
            int seg = (idx & 7) * 16;                    // byte within 128B row
            uint32_t d = st + (isB ? 16384u : 0u) + SWZ((uint32_t)(row * 128 + seg));
            const char* p = (isB ? Bbase : Abase) + (size_t)row * (KCAT * 2) + coff + seg;
            CP16(d, p);
        }
    };

    // warp tiling: 4 warps along M (32 rows each), 2 along N (64 cols each)
    const int warpM = w & 3;
    const int warpN = w >> 2;
    const int m0w = warpM * 32;
    const int n0w = warpN * 64;

    // per-lane ldmatrix byte offsets (before swizzle)
    const uint32_t aRow = (uint32_t)((m0w + (lane & 15)) * 128 + (lane >> 4) * 16);
    const uint32_t bRow = (uint32_t)((n0w + (lane & 15)) * 128 + (lane >> 4) * 16);

    float acc[2][8][4];
#pragma unroll
    for (int i = 0; i < 2; i++)
#pragma unroll
        for (int j = 0; j < 8; j++)
#pragma unroll
            for (int r = 0; r < 4; r++) acc[i][j][r] = 0.f;

    issue_loads(0, 0); CP_COMMIT();
    issue_loads(1, 1); CP_COMMIT();

    for (int c = 0; c < NCHNK; c++) {
        if (c >= NCHNK - 1) { CP_WAIT(0); } else { CP_WAIT(1); }
        __syncthreads();

        if (c + 2 < NCHNK) { issue_loads(c + 2, (c + 2) % 3); CP_COMMIT(); }

        const uint32_t Ast = sb + (uint32_t)(c % 3) * STAGE_SZ;
        const uint32_t Bst = Ast + 16384u;

#pragma unroll
        for (int ks = 0; ks < 4; ks++) {
            uint32_t a[2][4];
#pragma unroll
            for (int i = 0; i < 2; i++) {
                uint32_t ad = Ast + SWZ(aRow + (uint32_t)(i * 2048 + ks * 32));
                LDSM4(a[i][0], a[i][1], a[i][2], a[i][3], ad);
            }
            uint32_t bf[8][2];
#pragma unroll
            for (int jj = 0; jj < 4; jj++) {
                uint32_t bd = Bst + SWZ(bRow + (uint32_t)(jj * 2048 + ks * 32));
                uint32_t r0, r1, r2, r3;
                LDSM4(r0, r1, r2, r3, bd);
                bf[2*jj][0]   = r0; bf[2*jj][1]   = r2;
                bf[2*jj+1][0] = r1; bf[2*jj+1][1] = r3;
            }
#pragma unroll
            for (int i = 0; i < 2; i++)
#pragma unroll
                for (int j = 0; j < 8; j++)
                    MMA16816(acc[i][j], a[i], bf[j]);
        }
        __syncthreads();
    }

    // ---- epilogue: bias + sigmoid, direct coalesced float2 stores ----
#pragma unroll
    for (int i = 0; i < 2; i++) {
        int row = m0 + m0w + i * 16 + (lane >> 2);
#pragma unroll
        for (int j = 0; j < 8; j++) {
            int col = n0 + n0w + j * 8 + (lane & 3) * 2;
            if (col >= N) continue;                     // N is even -> col+1 < N too
            float bv0 = bias[col], bv1 = bias[col + 1];
            float2 v0, v1;
            v0.x = 1.f / (1.f + expf(-(acc[i][j][0] + bv0)));
            v0.y = 1.f / (1.f + expf(-(acc[i][j][1] + bv1)));
            v1.x = 1.f / (1.f + expf(-(acc[i][j][2] + bv0)));
            v1.y = 1.f / (1.f + expf(-(acc[i][j][3] + bv1)));
            *(float2*)(Z + (size_t)row * N + col)       = v0;
            *(float2*)(Z + (size_t)(row + 8) * N + col) = v1;
        }
    }
}

// ---------------------------------------------------------------------------
// Loss epilogue (unchanged; 52.6us measured)
// ---------------------------------------------------------------------------
__device__ __forceinline__ float blockMax(float v, float* red) {
    int t = threadIdx.x;
    red[t] = v; __syncthreads();
    for (int s = 128; s > 0; s >>= 1) {
        if (t < s) red[t] = fmaxf(red[t], red[t + s]);
        __syncthreads();
    }
    float r = red[0]; __syncthreads();
    return r;
}
__device__ __forceinline__ float blockSum(float v, float* red) {
    int t = threadIdx.x;
    red[t] = v; __syncthreads();
    for (int s = 128; s > 0; s >>= 1) {
        if (t < s) red[t] += red[t + s];
        __syncthreads();
    }
    float r = red[0]; __syncthreads();
    return r;
}

__global__ __launch_bounds__(256)
void epilogue_kernel(const float* __restrict__ z1,
                     const float* __restrict__ z2,
                     const int*   __restrict__ labels,
                     float* outZ,
                     float* __restrict__ loss_rows)
{
    __shared__ float s1[N1C];
    __shared__ float s2[N2C];
    __shared__ float s3[N2C];
    __shared__ float red[256];
    __shared__ float slab;

    const int b = blockIdx.x;
    const int t = threadIdx.x;
    const int lab  = labels[b];
    const int lab1 = lab / 100;
    const int lab2 = lab / 10;

    float* orow = outZ + (size_t)b * N3C;

    for (int i = t; i < N1C; i += 256) s1[i] = z1[(size_t)b * N1C + i];
    for (int i = t; i < N2C; i += 256) s2[i] = z2[(size_t)b * N2C + i];
    for (int i = t; i < N2C; i += 256) s3[i] = orow[i];
    __syncthreads();

    float lmax = -1e30f;
    for (int k = t; k < N1C; k += 256) lmax = fmaxf(lmax, s1[k]);
    float m1 = blockMax(lmax, red);
    float lsum = 0.f;
    for (int k = t; k < N1C; k += 256) lsum += expf(s1[k] - m1);
    float sum1 = blockSum(lsum, red);
    float loss1 = logf(sum1) + m1 - s1[lab1];

    lmax = -1e30f;
    for (int k = t; k < N2C; k += 256) lmax = fmaxf(lmax, s2[k / 10] * s2[k]);
    float m2 = blockMax(lmax, red);
    lsum = 0.f;
    for (int k = t; k < N2C; k += 256) lsum += expf(s2[k / 10] * s2[k] - m2);
    float sum2 = blockSum(lsum, red);
    float loss2 = logf(sum2) + m2 - s2[lab2 / 10] * s2[lab2];

    lmax = -1e30f;
    for (int k = t; k < N3C; k += 256) {
        float z = (k < N2C) ? s3[k] : orow[k];
        float l = s3[k / 100] * s3[k / 10] * z;
        orow[k] = l;
        if (k == lab) slab = l;
        lmax = fmaxf(lmax, l);
    }
    float m3 = blockMax(lmax, red);
    lsum = 0.f;
    for (int k = t; k < N3C; k += 256) lsum += expf(orow[k] - m3);
    float sum3 = blockSum(lsum, red);
    float loss3 = logf(sum3) + m3 - slab;

    if (t == 0) loss_rows[b] = loss1 + loss2 + loss3;
}

__global__ __launch_bounds__(256)
void loss_reduce_kernel(const float* __restrict__ lr, float* __restrict__ dst, int B)
{
    __shared__ float red[256];
    int t = threadIdx.x;
    float s = 0.f;
    for (int i = t; i < B; i += 256) s += lr[i];
    red[t] = s; __syncthreads();
    for (int k = 128; k > 0; k >>= 1) {
        if (t < k) red[t] += red[t + k];
        __syncthreads();
    }
    if (t == 0) *dst = red[0] / (float)B;
}

// ---------------------------------------------------------------------------
extern "C" void kernel_launch(void* const* d_in, const int* in_sizes, int n_in,
                              void* d_out, int out_size)
{
    const float* x      = (const float*)d_in[0];
    const int*   labels = (const int*)  d_in[1];
    const float* W1     = (const float*)d_in[2];
    const float* b1     = (const float*)d_in[3];
    const float* W2     = (const float*)d_in[4];
    const float* b2     = (const float*)d_in[5];
    const float* W3     = (const float*)d_in[6];
    const float* b3     = (const float*)d_in[7];

    int B = in_sizes[0] / HID;
    if (B > BMAX) B = BMAX;

    float* out = (float*)d_out;

    float *z1p, *z2p, *z3p, *lrp;
    __nv_bfloat16 *xcp, *w1p, *w2p, *w3p;
    cudaGetSymbolAddress((void**)&z1p, g_z1);
    cudaGetSymbolAddress((void**)&z2p, g_z2);
    cudaGetSymbolAddress((void**)&z3p, g_z3);
    cudaGetSymbolAddress((void**)&lrp, g_lossrows);
    cudaGetSymbolAddress((void**)&xcp, g_xc);
    cudaGetSymbolAddress((void**)&w1p, g_w1c);
    cudaGetSymbolAddress((void**)&w2p, g_w2c);
    cudaGetSymbolAddress((void**)&w3p, g_w3c);

    // operand conversion: X' = [hi|hi|lo] (lo_slot=2), W' = [hi|lo|hi] (lo_slot=1)
    {
        int tot = B * (HID / 4);
        convert_cat_kernel<<<(tot + 255) / 256, 256>>>(x, xcp, B, B, 2);
    }
    {
        int tot = N1P * (HID / 4);
        convert_cat_kernel<<<(tot + 255) / 256, 256>>>(W1, w1p, N1C, N1P, 1);
    }
    {
        int tot = N2P * (HID / 4);
        convert_cat_kernel<<<(tot + 255) / 256, 256>>>(W2, w2p, N2C, N2P, 1);
    }
    {
        int tot = N3P * (HID / 4);
        convert_cat_kernel<<<(tot + 255) / 256, 256>>>(W3, w3p, N3C, N3P, 1);
    }

    const size_t LE = (size_t)B * N3C;
    float* zdst = ((size_t)out_size >= LE) ? out : z3p;

    cudaFuncSetAttribute(gemm_mma_kernel, cudaFuncAttributeMaxDynamicSharedMemorySize, SMEM_BYTES);
    gemm_mma_kernel<<<dim3(NT_COL, B / 128), 256, SMEM_BYTES>>>(
        xcp,
        w1p, b1, z1p,
        w2p, b2, z2p,
        w3p, b3, zdst);

    epilogue_kernel<<<B, 256>>>(z1p, z2p, labels, zdst, lrp);

    if ((size_t)out_size > LE) {
        loss_reduce_kernel<<<1, 256>>>(lrp, out + LE, B);
    } else if ((size_t)out_size < LE && out_size >= 1) {
        loss_reduce_kernel<<<1, 256>>>(lrp, out, B);
    }
}

// round 4
// speedup vs baseline: 4.5664x; 1.4312x over previous
#include <cuda_runtime.h>
#include <cuda_fp16.h>
#include <cuda_bf16.h>
#include <math.h>
#include <stdint.h>

// Problem constants
#define HID   1024
#define KCAT  2048            // 2 * HID: A' = [xh | xl] interleaved per 128B segment
#define N1C   28
#define N2C   280
#define N3C   2800
#define BMAX  4096
// per-level N padded to 128-col tiles
#define N1P   128
#define N2P   384
#define N3P   2816
#define NT_COL 26             // 1 + 3 + 22 column tiles

#define BMt   256
#define BNt   128
#define NCH   32              // A chunks of 64 fp16 (128B) over K=2048

// ---------------------------------------------------------------------------
// Scratch (__device__ globals; allocation-free)
// ---------------------------------------------------------------------------
__device__ float g_z1[BMAX * N1C];
__device__ float g_z2[BMAX * N2C];
__device__ float g_z3[BMAX * N3C];
__device__ float g_lossrows[BMAX];

__device__ alignas(256) __half g_xc [BMAX * KCAT];   // interleaved [xh seg | xl seg] x16
__device__ alignas(256) __half g_w1c[N1P  * HID];
__device__ alignas(256) __half g_w2c[N2P  * HID];
__device__ alignas(256) __half g_w3c[N3P  * HID];

// ---------------------------------------------------------------------------
// helpers
// ---------------------------------------------------------------------------
__device__ __forceinline__ uint32_t smem_u32(const void* p) {
    uint32_t a;
    asm("{ .reg .u64 t; cvta.to.shared.u64 t, %1; cvt.u32.u64 %0, t; }" : "=r"(a) : "l"(p));
    return a;
}
#define SWZ(off) ((off) ^ (((off) >> 3) & 0x70))

#define CP16(dst, src) \
    asm volatile("cp.async.cg.shared.global [%0], [%1], 16;" :: "r"(dst), "l"(src))
#define CP_COMMIT() asm volatile("cp.async.commit_group;" ::: "memory")
#define CP_WAIT(n)  asm volatile("cp.async.wait_group %0;" :: "n"(n) : "memory")

#define LDSM4(r0, r1, r2, r3, addr) \
    asm volatile("ldmatrix.sync.aligned.m8n8.x4.shared.b16 {%0,%1,%2,%3}, [%4];" \
                 : "=r"(r0), "=r"(r1), "=r"(r2), "=r"(r3) : "r"(addr))

#define MMA16816(d, a, b) \
    asm volatile("mma.sync.aligned.m16n8k16.row.col.f32.f16.f16.f32 " \
                 "{%0,%1,%2,%3}, {%4,%5,%6,%7}, {%8,%9}, {%0,%1,%2,%3};" \
                 : "+f"((d)[0]), "+f"((d)[1]), "+f"((d)[2]), "+f"((d)[3]) \
                 : "r"((a)[0]), "r"((a)[1]), "r"((a)[2]), "r"((a)[3]), \
                   "r"((b)[0]), "r"((b)[1]))

// ---------------------------------------------------------------------------
// x [B,1024] f32 -> A' [B,2048] fp16, interleaved: per 64-col segment p:
// halves [p*128 .. p*128+63] = xh of cols p*64.., [p*128+64 ..+127] = xl.
// ---------------------------------------------------------------------------
__global__ __launch_bounds__(256)
void convert_x_kernel(const float* __restrict__ src, __half* __restrict__ dst, int B)
{
    int i = blockIdx.x * blockDim.x + threadIdx.x;   // one per 4 fp32
    int total = B * (HID / 4);
    if (i >= total) return;
    int row = i >> 8;                // /256
    int k4  = (i & 255) * 4;         // fp32 col
    float4 v = *(const float4*)(src + (size_t)row * HID + k4);

    __half h[4], l[4];
    float vv[4] = {v.x, v.y, v.z, v.w};
#pragma unroll
    for (int t = 0; t < 4; t++) {
        h[t] = __float2half_rn(vv[t]);
        l[t] = __float2half_rn(vv[t] - __half2float(h[t]));
    }
    int p = k4 >> 6;                 // segment
    int o = k4 & 63;                 // offset within segment (halves)
    __half* base = dst + (size_t)row * KCAT + p * 128;
    *(__half2*)(base + o)          = __half2{h[0], h[1]};
    *(__half2*)(base + o + 2)      = __half2{h[2], h[3]};
    *(__half2*)(base + 64 + o)     = __half2{l[0], l[1]};
    *(__half2*)(base + 64 + o + 2) = __half2{l[2], l[3]};
}

// W [rows_valid,1024] f32 -> fp16 [rows_total,1024], zero-padded rows
__global__ __launch_bounds__(256)
void convert_w_kernel(const float* __restrict__ src, __half* __restrict__ dst,
                      int rows_valid, int rows_total)
{
    int i = blockIdx.x * blockDim.x + threadIdx.x;
    int total = rows_total * (HID / 4);
    if (i >= total) return;
    int row = i >> 8;
    int k4  = (i & 255) * 4;
    float4 v = make_float4(0.f, 0.f, 0.f, 0.f);
    if (row < rows_valid) v = *(const float4*)(src + (size_t)row * HID + k4);
    __half2* d2 = (__half2*)(dst + (size_t)row * HID + k4);
    d2[0] = __half2{__float2half_rn(v.x), __float2half_rn(v.y)};
    d2[1] = __half2{__float2half_rn(v.z), __float2half_rn(v.w)};
}

// ---------------------------------------------------------------------------
// Fused fp16 mma.sync GEMM: Z = sigmoid((xh+xl) @ W^T + b).
// CTA 256x128, chunk 64 fp16 (A), B chunk shared by chunk pairs (c>>1).
// 512 threads, 16 warps (warp tile 64x32), 4-stage cp.async.
// grid = (26, B/256).
// ---------------------------------------------------------------------------
#define ASTG 32768u
#define BSTG 16384u
#define B_OFF (4u * ASTG)
#define SMEM_BYTES (1024u + 4u * ASTG + 4u * BSTG)   // 197632

__global__ __launch_bounds__(512, 1)
void gemm_mma_kernel(const __half* __restrict__ xc,
                     const __half* __restrict__ w1c, const float* __restrict__ b1, float* __restrict__ z1,
                     const __half* __restrict__ w2c, const float* __restrict__ b2, float* __restrict__ z2,
                     const __half* __restrict__ w3c, const float* __restrict__ b3, float* __restrict__ z3)
{
    extern __shared__ char smem[];
    const uint32_t sb = (smem_u32(smem) + 1023u) & ~1023u;

    const int tid  = threadIdx.x;
    const int lane = tid & 31;
    const int w    = tid >> 5;
    const int brow = blockIdx.y;
    const int bcol = blockIdx.x;

    const __half* wc; const float* bias; float* Z; int N, lcol;
    if (bcol == 0)      { wc = w1c; bias = b1; Z = z1; N = N1C; lcol = 0; }
    else if (bcol <= 3) { wc = w2c; bias = b2; Z = z2; N = N2C; lcol = bcol - 1; }
    else                { wc = w3c; bias = b3; Z = z3; N = N3C; lcol = bcol - 4; }

    const int m0 = brow * BMt;
    const int n0 = lcol * BNt;

    const char* Abase = (const char*)(xc + (size_t)m0 * KCAT);   // 4096 B/row
    const char* Bbase = (const char*)(wc + (size_t)n0 * HID);    // 2048 B/row

    // ---- loader: A every chunk (2048 CP16), B on even chunks (1024 CP16) ----
    auto issue_loads = [&](int c) {
        const uint32_t Ast = sb + (uint32_t)(c & 3) * ASTG;
        const int coff = c * 128;
#pragma unroll
        for (int it = 0; it < 4; it++) {
            int i = tid + it * 512;                  // 0..2047
            int row = i >> 3;
            int seg = (i & 7) * 16;
            uint32_t d = Ast + SWZ((uint32_t)(row * 128 + seg));
            CP16(d, Abase + (size_t)row * 4096 + coff + seg);
        }
        if ((c & 1) == 0) {
            const uint32_t Bst = sb + B_OFF + (uint32_t)((c >> 1) & 3) * BSTG;
            const int bcoff = (c >> 1) * 128;
#pragma unroll
            for (int it = 0; it < 2; it++) {
                int i = tid + it * 512;              // 0..1023
                int row = i >> 3;
                int seg = (i & 7) * 16;
                uint32_t d = Bst + SWZ((uint32_t)(row * 128 + seg));
                CP16(d, Bbase + (size_t)row * 2048 + bcoff + seg);
            }
        }
        CP_COMMIT();
    };

    // warp tiling: 4 warps along M (64 rows), 4 along N (32 cols)
    const int warpM = w & 3;
    const int warpN = w >> 2;
    const int m0w = warpM * 64;
    const int n0w = warpN * 32;

    const uint32_t aRow = (uint32_t)((m0w + (lane & 15)) * 128 + (lane >> 4) * 16);
    const uint32_t bRow = (uint32_t)((n0w + (lane & 15)) * 128 + (lane >> 4) * 16);

    float acc[4][4][4];
#pragma unroll
    for (int i = 0; i < 4; i++)
#pragma unroll
        for (int j = 0; j < 4; j++)
#pragma unroll
            for (int r = 0; r < 4; r++) acc[i][j][r] = 0.f;

    issue_loads(0); issue_loads(1); issue_loads(2);

    for (int c = 0; c < NCH; c++) {
        if (c < NCH - 2)      { CP_WAIT(2); }
        else if (c == NCH - 2){ CP_WAIT(1); }
        else                  { CP_WAIT(0); }
        __syncthreads();

        if (c + 3 < NCH) issue_loads(c + 3);

        const uint32_t Ast = sb + (uint32_t)(c & 3) * ASTG;
        const uint32_t Bst = sb + B_OFF + (uint32_t)((c >> 1) & 3) * BSTG;

#pragma unroll
        for (int ks = 0; ks < 4; ks++) {
            uint32_t a[4][4];
#pragma unroll
            for (int i = 0; i < 4; i++) {
                uint32_t ad = Ast + SWZ(aRow + (uint32_t)(i * 2048 + ks * 32));
                LDSM4(a[i][0], a[i][1], a[i][2], a[i][3], ad);
            }
            uint32_t bf[4][2];
#pragma unroll
            for (int jj = 0; jj < 2; jj++) {
                uint32_t bd = Bst + SWZ(bRow + (uint32_t)(jj * 2048 + ks * 32));
                uint32_t r0, r1, r2, r3;
                LDSM4(r0, r1, r2, r3, bd);
                bf[2*jj][0]   = r0; bf[2*jj][1]   = r2;
                bf[2*jj+1][0] = r1; bf[2*jj+1][1] = r3;
            }
#pragma unroll
            for (int i = 0; i < 4; i++)
#pragma unroll
                for (int j = 0; j < 4; j++)
                    MMA16816(acc[i][j], a[i], bf[j]);
        }
        __syncthreads();
    }

    // ---- epilogue: bias + sigmoid, coalesced float2 stores ----
#pragma unroll
    for (int i = 0; i < 4; i++) {
        int row = m0 + m0w + i * 16 + (lane >> 2);
#pragma unroll
        for (int j = 0; j < 4; j++) {
            int col = n0 + n0w + j * 8 + (lane & 3) * 2;
            if (col >= N) continue;
            float bv0 = bias[col], bv1 = bias[col + 1];
            float2 v0, v1;
            v0.x = 1.f / (1.f + expf(-(acc[i][j][0] + bv0)));
            v0.y = 1.f / (1.f + expf(-(acc[i][j][1] + bv1)));
            v1.x = 1.f / (1.f + expf(-(acc[i][j][2] + bv0)));
            v1.y = 1.f / (1.f + expf(-(acc[i][j][3] + bv1)));
            *(float2*)(Z + (size_t)row * N + col)       = v0;
            *(float2*)(Z + (size_t)(row + 8) * N + col) = v1;
        }
    }
}

// ---------------------------------------------------------------------------
// Loss epilogue v2: no max shift (all logits in (0,1)), single fused L3 pass,
// shuffle-based reductions.
// ---------------------------------------------------------------------------
__device__ __forceinline__ float blockSum256(float v, float* red) {
    int t = threadIdx.x;
#pragma unroll
    for (int off = 16; off; off >>= 1) v += __shfl_xor_sync(0xFFFFFFFFu, v, off);
    if ((t & 31) == 0) red[t >> 5] = v;
    __syncthreads();
    if (t == 0) {
        float s = 0.f;
#pragma unroll
        for (int k = 0; k < 8; k++) s += red[k];
        red[0] = s;
    }
    __syncthreads();
    float r = red[0];
    __syncthreads();
    return r;
}

__global__ __launch_bounds__(256)
void epilogue_kernel(const float* __restrict__ z1,
                     const float* __restrict__ z2,
                     const int*   __restrict__ labels,
                     float* outZ,
                     float* __restrict__ loss_rows)
{
    __shared__ float s1[N1C];
    __shared__ float s2[N2C];
    __shared__ float s3[N2C];
    __shared__ float red[8];
    __shared__ float slab;

    const int b = blockIdx.x;
    const int t = threadIdx.x;
    const int lab  = labels[b];
    const int lab1 = lab / 100;
    const int lab2 = lab / 10;

    float* orow = outZ + (size_t)b * N3C;

    if (t < N1C) s1[t] = z1[(size_t)b * N1C + t];
    for (int i = t; i < N2C; i += 256) s2[i] = z2[(size_t)b * N2C + i];
    for (int i = t; i < N2C; i += 256) s3[i] = orow[i];
    __syncthreads();

    // level 1: logits = z1 in (0,1) -> no max shift needed
    float e1 = 0.f;
    if (t < N1C) e1 = __expf(s1[t]);
    // level 2
    float e2 = 0.f;
    for (int k = t; k < N2C; k += 256) e2 += __expf(s2[k / 10] * s2[k]);
    // level 3: fused transform + sum (single global read+write pass)
    float e3 = 0.f;
    for (int k = t; k < N3C; k += 256) {
        float z = (k < N2C) ? s3[k] : orow[k];
        float l = s3[k / 100] * s3[k / 10] * z;
        orow[k] = l;
        if (k == lab) slab = l;
        e3 += __expf(l);
    }

    float sum1 = blockSum256(e1, red);
    float sum2 = blockSum256(e2, red);
    float sum3 = blockSum256(e3, red);

    if (t == 0) {
        float loss1 = logf(sum1) - s1[lab1];
        float loss2 = logf(sum2) - s2[lab2 / 10] * s2[lab2];
        float loss3 = logf(sum3) - slab;
        loss_rows[b] = loss1 + loss2 + loss3;
    }
}

__global__ __launch_bounds__(256)
void loss_reduce_kernel(const float* __restrict__ lr, float* __restrict__ dst, int B)
{
    __shared__ float red[256];
    int t = threadIdx.x;
    float s = 0.f;
    for (int i = t; i < B; i += 256) s += lr[i];
    red[t] = s; __syncthreads();
    for (int k = 128; k > 0; k >>= 1) {
        if (t < k) red[t] += red[t + k];
        __syncthreads();
    }
    if (t == 0) *dst = red[0] / (float)B;
}

// ---------------------------------------------------------------------------
extern "C" void kernel_launch(void* const* d_in, const int* in_sizes, int n_in,
                              void* d_out, int out_size)
{
    const float* x      = (const float*)d_in[0];
    const int*   labels = (const int*)  d_in[1];
    const float* W1     = (const float*)d_in[2];
    const float* b1     = (const float*)d_in[3];
    const float* W2     = (const float*)d_in[4];
    const float* b2     = (const float*)d_in[5];
    const float* W3     = (const float*)d_in[6];
    const float* b3     = (const float*)d_in[7];

    int B = in_sizes[0] / HID;
    if (B > BMAX) B = BMAX;

    float* out = (float*)d_out;

    float *z1p, *z2p, *z3p, *lrp;
    __half *xcp, *w1p, *w2p, *w3p;
    cudaGetSymbolAddress((void**)&z1p, g_z1);
    cudaGetSymbolAddress((void**)&z2p, g_z2);
    cudaGetSymbolAddress((void**)&z3p, g_z3);
    cudaGetSymbolAddress((void**)&lrp, g_lossrows);
    cudaGetSymbolAddress((void**)&xcp, g_xc);
    cudaGetSymbolAddress((void**)&w1p, g_w1c);
    cudaGetSymbolAddress((void**)&w2p, g_w2c);
    cudaGetSymbolAddress((void**)&w3p, g_w3c);

    {
        int tot = B * (HID / 4);
        convert_x_kernel<<<(tot + 255) / 256, 256>>>(x, xcp, B);
    }
    {
        int tot = N1P * (HID / 4);
        convert_w_kernel<<<(tot + 255) / 256, 256>>>(W1, w1p, N1C, N1P);
    }
    {
        int tot = N2P * (HID / 4);
        convert_w_kernel<<<(tot + 255) / 256, 256>>>(W2, w2p, N2C, N2P);
    }
    {
        int tot = N3P * (HID / 4);
        convert_w_kernel<<<(tot + 255) / 256, 256>>>(W3, w3p, N3C, N3P);
    }

    const size_t LE = (size_t)B * N3C;
    float* zdst = ((size_t)out_size >= LE) ? out : z3p;

    cudaFuncSetAttribute(gemm_mma_kernel, cudaFuncAttributeMaxDynamicSharedMemorySize, SMEM_BYTES);
    gemm_mma_kernel<<<dim3(NT_COL, B / BMt), 512, SMEM_BYTES>>>(
        xcp,
        w1p, b1, z1p,
        w2p, b2, z2p,
        w3p, b3, zdst);

    epilogue_kernel<<<B, 256>>>(z1p, z2p, labels, zdst, lrp);

    if ((size_t)out_size > LE) {
        loss_reduce_kernel<<<1, 256>>>(lrp, out + LE, B);
    } else if ((size_t)out_size < LE && out_size >= 1) {
        loss_reduce_kernel<<<1, 256>>>(lrp, out, B);
    }
}

// round 5
// speedup vs baseline: 7.5172x; 1.6462x over previous
#include <cuda_runtime.h>
#include <cuda_fp16.h>
#include <math.h>
#include <stdint.h>

// Problem constants
#define HID   1024
#define N1C   28
#define N2C   280
#define N3C   2800
#define BMAX  4096
// per-level N padded to 128-col tiles
#define N1P   128
#define N2P   384
#define N3P   2816
#define NT_COL 26             // 1 + 3 + 22 column tiles

#define BMt   256
#define BNt   128
#define NCH   16              // K chunks of 64 fp16 (128B) over K=1024

// ---------------------------------------------------------------------------
// Scratch (__device__ globals; allocation-free)
// ---------------------------------------------------------------------------
__device__ float g_z1[BMAX * N1C];
__device__ float g_z2[BMAX * N2C];
__device__ float g_z3[BMAX * N3C];
__device__ float g_lossrows[BMAX];

__device__ alignas(256) __half g_xc [BMAX * HID];
__device__ alignas(256) __half g_w1c[N1P  * HID];
__device__ alignas(256) __half g_w2c[N2P  * HID];
__device__ alignas(256) __half g_w3c[N3P  * HID];

// ---------------------------------------------------------------------------
// helpers
// ---------------------------------------------------------------------------
__device__ __forceinline__ uint32_t smem_u32(const void* p) {
    uint32_t a;
    asm("{ .reg .u64 t; cvta.to.shared.u64 t, %1; cvt.u32.u64 %0, t; }" : "=r"(a) : "l"(p));
    return a;
}
#define SWZ(off) ((off) ^ (((off) >> 3) & 0x70))

#define CP16(dst, src) \
    asm volatile("cp.async.cg.shared.global [%0], [%1], 16;" :: "r"(dst), "l"(src))
#define CP_COMMIT() asm volatile("cp.async.commit_group;" ::: "memory")
#define CP_WAIT(n)  asm volatile("cp.async.wait_group %0;" :: "n"(n) : "memory")

#define LDSM4(r0, r1, r2, r3, addr) \
    asm volatile("ldmatrix.sync.aligned.m8n8.x4.shared.b16 {%0,%1,%2,%3}, [%4];" \
                 : "=r"(r0), "=r"(r1), "=r"(r2), "=r"(r3) : "r"(addr))

#define MMA16816(d, a, b) \
    asm volatile("mma.sync.aligned.m16n8k16.row.col.f32.f16.f16.f32 " \
                 "{%0,%1,%2,%3}, {%4,%5,%6,%7}, {%8,%9}, {%0,%1,%2,%3};" \
                 : "+f"((d)[0]), "+f"((d)[1]), "+f"((d)[2]), "+f"((d)[3]) \
                 : "r"((a)[0]), "r"((a)[1]), "r"((a)[2]), "r"((a)[3]), \
                   "r"((b)[0]), "r"((b)[1]))

// ---------------------------------------------------------------------------
// Fused conversion: one block (256 thr) per row; 4 fp32 -> 4 fp16 per thread.
// Regions: x (B rows), W1 (N1P rows, valid N1C), W2, W3. Padded rows -> 0.
// ---------------------------------------------------------------------------
__global__ __launch_bounds__(256)
void convert_all_kernel(const float* __restrict__ x,
                        const float* __restrict__ W1,
                        const float* __restrict__ W2,
                        const float* __restrict__ W3,
                        __half* __restrict__ xc, __half* __restrict__ w1,
                        __half* __restrict__ w2, __half* __restrict__ w3,
                        int B)
{
    int blk = blockIdx.x;
    const float* src; __half* dst; int row, valid;
    if (blk < B)                         { src = x;  dst = xc; row = blk;                   valid = B;   }
    else if (blk < B + N1P)              { src = W1; dst = w1; row = blk - B;               valid = N1C; }
    else if (blk < B + N1P + N2P)        { src = W2; dst = w2; row = blk - B - N1P;         valid = N2C; }
    else                                 { src = W3; dst = w3; row = blk - B - N1P - N2P;   valid = N3C; }

    int k4 = threadIdx.x * 4;
    float4 v = make_float4(0.f, 0.f, 0.f, 0.f);
    if (row < valid) v = *(const float4*)(src + (size_t)row * HID + k4);
    __half2* d2 = (__half2*)(dst + (size_t)row * HID + k4);
    d2[0] = __half2{__float2half_rn(v.x), __float2half_rn(v.y)};
    d2[1] = __half2{__float2half_rn(v.z), __float2half_rn(v.w)};
}

// ---------------------------------------------------------------------------
// Fused fp16 mma.sync GEMM: Z = sigmoid(x @ W^T + b), K = 1024.
// CTA 256x128, K-chunk 64, 512 threads, 16 warps (warp tile 64x32), 4 stages.
// grid = (26, B/256).
// ---------------------------------------------------------------------------
#define ASTG 32768u
#define BSTG 16384u
#define B_OFF (4u * ASTG)
#define SMEM_BYTES (1024u + 4u * ASTG + 4u * BSTG)   // 197632

__global__ __launch_bounds__(512, 1)
void gemm_mma_kernel(const __half* __restrict__ xc,
                     const __half* __restrict__ w1c, const float* __restrict__ b1, float* __restrict__ z1,
                     const __half* __restrict__ w2c, const float* __restrict__ b2, float* __restrict__ z2,
                     const __half* __restrict__ w3c, const float* __restrict__ b3, float* __restrict__ z3)
{
    extern __shared__ char smem[];
    const uint32_t sb = (smem_u32(smem) + 1023u) & ~1023u;

    const int tid  = threadIdx.x;
    const int lane = tid & 31;
    const int w    = tid >> 5;
    const int brow = blockIdx.y;
    const int bcol = blockIdx.x;

    const __half* wc; const float* bias; float* Z; int N, lcol;
    if (bcol == 0)      { wc = w1c; bias = b1; Z = z1; N = N1C; lcol = 0; }
    else if (bcol <= 3) { wc = w2c; bias = b2; Z = z2; N = N2C; lcol = bcol - 1; }
    else                { wc = w3c; bias = b3; Z = z3; N = N3C; lcol = bcol - 4; }

    const int m0 = brow * BMt;
    const int n0 = lcol * BNt;

    const char* Abase = (const char*)(xc + (size_t)m0 * HID);    // 2048 B/row
    const char* Bbase = (const char*)(wc + (size_t)n0 * HID);    // 2048 B/row

    // ---- loader: A (2048 CP16) + B (1024 CP16) per chunk ----
    auto issue_loads = [&](int c) {
        const uint32_t Ast = sb + (uint32_t)(c & 3) * ASTG;
        const int coff = c * 128;
#pragma unroll
        for (int it = 0; it < 4; it++) {
            int i = tid + it * 512;                  // 0..2047
            int row = i >> 3;
            int seg = (i & 7) * 16;
            uint32_t d = Ast + SWZ((uint32_t)(row * 128 + seg));
            CP16(d, Abase + (size_t)row * 2048 + coff + seg);
        }
        const uint32_t Bst = sb + B_OFF + (uint32_t)(c & 3) * BSTG;
#pragma unroll
        for (int it = 0; it < 2; it++) {
            int i = tid + it * 512;                  // 0..1023
            int row = i >> 3;
            int seg = (i & 7) * 16;
            uint32_t d = Bst + SWZ((uint32_t)(row * 128 + seg));
            CP16(d, Bbase + (size_t)row * 2048 + coff + seg);
        }
        CP_COMMIT();
    };

    // warp tiling: 4 warps along M (64 rows), 4 along N (32 cols)
    const int warpM = w & 3;
    const int warpN = w >> 2;
    const int m0w = warpM * 64;
    const int n0w = warpN * 32;

    const uint32_t aRow = (uint32_t)((m0w + (lane & 15)) * 128 + (lane >> 4) * 16);
    const uint32_t bRow = (uint32_t)((n0w + (lane & 15)) * 128 + (lane >> 4) * 16);

    float acc[4][4][4];
#pragma unroll
    for (int i = 0; i < 4; i++)
#pragma unroll
        for (int j = 0; j < 4; j++)
#pragma unroll
            for (int r = 0; r < 4; r++) acc[i][j][r] = 0.f;

    issue_loads(0); issue_loads(1); issue_loads(2);

    for (int c = 0; c < NCH; c++) {
        if (c < NCH - 2)      { CP_WAIT(2); }
        else if (c == NCH - 2){ CP_WAIT(1); }
        else                  { CP_WAIT(0); }
        __syncthreads();

        if (c + 3 < NCH) issue_loads(c + 3);

        const uint32_t Ast = sb + (uint32_t)(c & 3) * ASTG;
        const uint32_t Bst = sb + B_OFF + (uint32_t)(c & 3) * BSTG;

#pragma unroll
        for (int ks = 0; ks < 4; ks++) {
            uint32_t a[4][4];
#pragma unroll
            for (int i = 0; i < 4; i++) {
                uint32_t ad = Ast + SWZ(aRow + (uint32_t)(i * 2048 + ks * 32));
                LDSM4(a[i][0], a[i][1], a[i][2], a[i][3], ad);
            }
            uint32_t bf[4][2];
#pragma unroll
            for (int jj = 0; jj < 2; jj++) {
                uint32_t bd = Bst + SWZ(bRow + (uint32_t)(jj * 2048 + ks * 32));
                uint32_t r0, r1, r2, r3;
                LDSM4(r0, r1, r2, r3, bd);
                bf[2*jj][0]   = r0; bf[2*jj][1]   = r2;
                bf[2*jj+1][0] = r1; bf[2*jj+1][1] = r3;
            }
#pragma unroll
            for (int i = 0; i < 4; i++)
#pragma unroll
                for (int j = 0; j < 4; j++)
                    MMA16816(acc[i][j], a[i], bf[j]);
        }
        __syncthreads();
    }

    // ---- epilogue: bias + sigmoid, coalesced float2 stores ----
#pragma unroll
    for (int i = 0; i < 4; i++) {
        int row = m0 + m0w + i * 16 + (lane >> 2);
#pragma unroll
        for (int j = 0; j < 4; j++) {
            int col = n0 + n0w + j * 8 + (lane & 3) * 2;
            if (col >= N) continue;
            float bv0 = bias[col], bv1 = bias[col + 1];
            float2 v0, v1;
            v0.x = 1.f / (1.f + expf(-(acc[i][j][0] + bv0)));
            v0.y = 1.f / (1.f + expf(-(acc[i][j][1] + bv1)));
            v1.x = 1.f / (1.f + expf(-(acc[i][j][2] + bv0)));
            v1.y = 1.f / (1.f + expf(-(acc[i][j][3] + bv1)));
            *(float2*)(Z + (size_t)row * N + col)       = v0;
            *(float2*)(Z + (size_t)(row + 8) * N + col) = v1;
        }
    }
}

// ---------------------------------------------------------------------------
// Loss epilogue: no max shift (all logits in (0,1)), single fused L3 pass.
// ---------------------------------------------------------------------------
__device__ __forceinline__ float blockSum256(float v, float* red) {
    int t = threadIdx.x;
#pragma unroll
    for (int off = 16; off; off >>= 1) v += __shfl_xor_sync(0xFFFFFFFFu, v, off);
    if ((t & 31) == 0) red[t >> 5] = v;
    __syncthreads();
    if (t == 0) {
        float s = 0.f;
#pragma unroll
        for (int k = 0; k < 8; k++) s += red[k];
        red[0] = s;
    }
    __syncthreads();
    float r = red[0];
    __syncthreads();
    return r;
}

__global__ __launch_bounds__(256)
void epilogue_kernel(const float* __restrict__ z1,
                     const float* __restrict__ z2,
                     const int*   __restrict__ labels,
                     float* outZ,
                     float* __restrict__ loss_rows)
{
    __shared__ float s1[N1C];
    __shared__ float s2[N2C];
    __shared__ float s3[N2C];
    __shared__ float red[8];
    __shared__ float slab;

    const int b = blockIdx.x;
    const int t = threadIdx.x;
    const int lab  = labels[b];
    const int lab1 = lab / 100;
    const int lab2 = lab / 10;

    float* orow = outZ + (size_t)b * N3C;

    if (t < N1C) s1[t] = z1[(size_t)b * N1C + t];
    for (int i = t; i < N2C; i += 256) s2[i] = z2[(size_t)b * N2C + i];
    for (int i = t; i < N2C; i += 256) s3[i] = orow[i];
    __syncthreads();

    float e1 = 0.f;
    if (t < N1C) e1 = __expf(s1[t]);
    float e2 = 0.f;
    for (int k = t; k < N2C; k += 256) e2 += __expf(s2[k / 10] * s2[k]);
    float e3 = 0.f;
    for (int k = t; k < N3C; k += 256) {
        float z = (k < N2C) ? s3[k] : orow[k];
        float l = s3[k / 100] * s3[k / 10] * z;
        orow[k] = l;
        if (k == lab) slab = l;
        e3 += __expf(l);
    }

    float sum1 = blockSum256(e1, red);
    float sum2 = blockSum256(e2, red);
    float sum3 = blockSum256(e3, red);

    if (t == 0) {
        float loss1 = logf(sum1) - s1[lab1];
        float loss2 = logf(sum2) - s2[lab2 / 10] * s2[lab2];
        float loss3 = logf(sum3) - slab;
        loss_rows[b] = loss1 + loss2 + loss3;
    }
}

__global__ __launch_bounds__(256)
void loss_reduce_kernel(const float* __restrict__ lr, float* __restrict__ dst, int B)
{
    __shared__ float red[256];
    int t = threadIdx.x;
    float s = 0.f;
    for (int i = t; i < B; i += 256) s += lr[i];
    red[t] = s; __syncthreads();
    for (int k = 128; k > 0; k >>= 1) {
        if (t < k) red[t] += red[t + k];
        __syncthreads();
    }
    if (t == 0) *dst = red[0] / (float)B;
}

// ---------------------------------------------------------------------------
extern "C" void kernel_launch(void* const* d_in, const int* in_sizes, int n_in,
                              void* d_out, int out_size)
{
    const float* x      = (const float*)d_in[0];
    const int*   labels = (const int*)  d_in[1];
    const float* W1     = (const float*)d_in[2];
    const float* b1     = (const float*)d_in[3];
    const float* W2     = (const float*)d_in[4];
    const float* b2     = (const float*)d_in[5];
    const float* W3     = (const float*)d_in[6];
    const float* b3     = (const float*)d_in[7];

    int B = in_sizes[0] / HID;
    if (B > BMAX) B = BMAX;

    float* out = (float*)d_out;

    float *z1p, *z2p, *z3p, *lrp;
    __half *xcp, *w1p, *w2p, *w3p;
    cudaGetSymbolAddress((void**)&z1p, g_z1);
    cudaGetSymbolAddress((void**)&z2p, g_z2);
    cudaGetSymbolAddress((void**)&z3p, g_z3);
    cudaGetSymbolAddress((void**)&lrp, g_lossrows);
    cudaGetSymbolAddress((void**)&xcp, g_xc);
    cudaGetSymbolAddress((void**)&w1p, g_w1c);
    cudaGetSymbolAddress((void**)&w2p, g_w2c);
    cudaGetSymbolAddress((void**)&w3p, g_w3c);

    // single fused conversion kernel: x + all three W's
    convert_all_kernel<<<B + N1P + N2P + N3P, 256>>>(x, W1, W2, W3, xcp, w1p, w2p, w3p, B);

    const size_t LE = (size_t)B * N3C;
    float* zdst = ((size_t)out_size >= LE) ? out : z3p;

    cudaFuncSetAttribute(gemm_mma_kernel, cudaFuncAttributeMaxDynamicSharedMemorySize, SMEM_BYTES);
    gemm_mma_kernel<<<dim3(NT_COL, B / BMt), 512, SMEM_BYTES>>>(
        xcp,
        w1p, b1, z1p,
        w2p, b2, z2p,
        w3p, b3, zdst);

    epilogue_kernel<<<B, 256>>>(z1p, z2p, labels, zdst, lrp);

    if ((size_t)out_size > LE) {
        loss_reduce_kernel<<<1, 256>>>(lrp, out + LE, B);
    } else if ((size_t)out_size < LE && out_size >= 1) {
        loss_reduce_kernel<<<1, 256>>>(lrp, out, B);
    }
}

// round 6
// speedup vs baseline: 7.6705x; 1.0204x over previous
#include <cuda_runtime.h>
#include <cuda_fp16.h>
#include <math.h>
#include <stdint.h>

// Problem constants
#define HID   1024
#define N1C   28
#define N2C   280
#define N3C   2800
#define BMAX  4096
// per-level N padded to 128-col tiles
#define N1P   128
#define N2P   384
#define N3P   2816
#define NT_COL 26             // 1 + 3 + 22 column tiles

#define BMt   256
#define BNt   128
#define NCH   16              // K chunks of 64 fp16 (128B) over K=1024

// ---------------------------------------------------------------------------
// Scratch (__device__ globals; allocation-free)
// ---------------------------------------------------------------------------
__device__ float g_z1[BMAX * N1C];
__device__ float g_z2[BMAX * N2C];
__device__ float g_z3[BMAX * N3C];
__device__ float g_lossrows[BMAX];

__device__ alignas(256) __half g_xc [BMAX * HID];
__device__ alignas(256) __half g_w1c[N1P  * HID];
__device__ alignas(256) __half g_w2c[N2P  * HID];
__device__ alignas(256) __half g_w3c[N3P  * HID];

// ---------------------------------------------------------------------------
// helpers
// ---------------------------------------------------------------------------
__device__ __forceinline__ uint32_t smem_u32(const void* p) {
    uint32_t a;
    asm("{ .reg .u64 t; cvta.to.shared.u64 t, %1; cvt.u32.u64 %0, t; }" : "=r"(a) : "l"(p));
    return a;
}
#define SWZ(off) ((off) ^ (((off) >> 3) & 0x70))

#define CP16(dst, src) \
    asm volatile("cp.async.cg.shared.global [%0], [%1], 16;" :: "r"(dst), "l"(src))
#define CP_COMMIT() asm volatile("cp.async.commit_group;" ::: "memory")
#define CP_WAIT(n)  asm volatile("cp.async.wait_group %0;" :: "n"(n) : "memory")

#define LDSM4(r0, r1, r2, r3, addr) \
    asm volatile("ldmatrix.sync.aligned.m8n8.x4.shared.b16 {%0,%1,%2,%3}, [%4];" \
                 : "=r"(r0), "=r"(r1), "=r"(r2), "=r"(r3) : "r"(addr))

#define MMA16816(d, a, b) \
    asm volatile("mma.sync.aligned.m16n8k16.row.col.f32.f16.f16.f32 " \
                 "{%0,%1,%2,%3}, {%4,%5,%6,%7}, {%8,%9}, {%0,%1,%2,%3};" \
                 : "+f"((d)[0]), "+f"((d)[1]), "+f"((d)[2]), "+f"((d)[3]) \
                 : "r"((a)[0]), "r"((a)[1]), "r"((a)[2]), "r"((a)[3]), \
                   "r"((b)[0]), "r"((b)[1]))

__device__ __forceinline__ float sigmoid_fast(float v) {
    return 1.f / (1.f + __expf(-v));
}

// ---------------------------------------------------------------------------
// Fused conversion: one block (256 thr) per row; 4 fp32 -> 4 fp16 per thread.
// ---------------------------------------------------------------------------
__global__ __launch_bounds__(256)
void convert_all_kernel(const float* __restrict__ x,
                        const float* __restrict__ W1,
                        const float* __restrict__ W2,
                        const float* __restrict__ W3,
                        __half* __restrict__ xc, __half* __restrict__ w1,
                        __half* __restrict__ w2, __half* __restrict__ w3,
                        int B)
{
    int blk = blockIdx.x;
    const float* src; __half* dst; int row, valid;
    if (blk < B)                         { src = x;  dst = xc; row = blk;                   valid = B;   }
    else if (blk < B + N1P)              { src = W1; dst = w1; row = blk - B;               valid = N1C; }
    else if (blk < B + N1P + N2P)        { src = W2; dst = w2; row = blk - B - N1P;         valid = N2C; }
    else                                 { src = W3; dst = w3; row = blk - B - N1P - N2P;   valid = N3C; }

    int k4 = threadIdx.x * 4;
    float4 v = make_float4(0.f, 0.f, 0.f, 0.f);
    if (row < valid) v = *(const float4*)(src + (size_t)row * HID + k4);
    __half2* d2 = (__half2*)(dst + (size_t)row * HID + k4);
    d2[0] = __half2{__float2half_rn(v.x), __float2half_rn(v.y)};
    d2[1] = __half2{__float2half_rn(v.z), __float2half_rn(v.w)};
}

// ---------------------------------------------------------------------------
// Fused fp16 mma.sync GEMM: Z = sigmoid(x @ W^T + b), K = 1024.
// CTA 256x128, K-chunk 64, 512 threads, 16 warps (warp tile 64x32), 4 stages.
// ---------------------------------------------------------------------------
#define ASTG 32768u
#define BSTG 16384u
#define B_OFF (4u * ASTG)
#define SMEM_BYTES (1024u + 4u * ASTG + 4u * BSTG)   // 197632

__global__ __launch_bounds__(512, 1)
void gemm_mma_kernel(const __half* __restrict__ xc,
                     const __half* __restrict__ w1c, const float* __restrict__ b1, float* __restrict__ z1,
                     const __half* __restrict__ w2c, const float* __restrict__ b2, float* __restrict__ z2,
                     const __half* __restrict__ w3c, const float* __restrict__ b3, float* __restrict__ z3)
{
    extern __shared__ char smem[];
    const uint32_t sb = (smem_u32(smem) + 1023u) & ~1023u;

    const int tid  = threadIdx.x;
    const int lane = tid & 31;
    const int w    = tid >> 5;
    const int brow = blockIdx.y;
    const int bcol = blockIdx.x;

    const __half* wc; const float* bias; float* Z; int N, lcol;
    if (bcol == 0)      { wc = w1c; bias = b1; Z = z1; N = N1C; lcol = 0; }
    else if (bcol <= 3) { wc = w2c; bias = b2; Z = z2; N = N2C; lcol = bcol - 1; }
    else                { wc = w3c; bias = b3; Z = z3; N = N3C; lcol = bcol - 4; }

    const int m0 = brow * BMt;
    const int n0 = lcol * BNt;

    const char* Abase = (const char*)(xc + (size_t)m0 * HID);    // 2048 B/row
    const char* Bbase = (const char*)(wc + (size_t)n0 * HID);    // 2048 B/row

    auto issue_loads = [&](int c) {
        const uint32_t Ast = sb + (uint32_t)(c & 3) * ASTG;
        const int coff = c * 128;
#pragma unroll
        for (int it = 0; it < 4; it++) {
            int i = tid + it * 512;                  // 0..2047
            int row = i >> 3;
            int seg = (i & 7) * 16;
            uint32_t d = Ast + SWZ((uint32_t)(row * 128 + seg));
            CP16(d, Abase + (size_t)row * 2048 + coff + seg);
        }
        const uint32_t Bst = sb + B_OFF + (uint32_t)(c & 3) * BSTG;
#pragma unroll
        for (int it = 0; it < 2; it++) {
            int i = tid + it * 512;                  // 0..1023
            int row = i >> 3;
            int seg = (i & 7) * 16;
            uint32_t d = Bst + SWZ((uint32_t)(row * 128 + seg));
            CP16(d, Bbase + (size_t)row * 2048 + coff + seg);
        }
        CP_COMMIT();
    };

    const int warpM = w & 3;
    const int warpN = w >> 2;
    const int m0w = warpM * 64;
    const int n0w = warpN * 32;

    const uint32_t aRow = (uint32_t)((m0w + (lane & 15)) * 128 + (lane >> 4) * 16);
    const uint32_t bRow = (uint32_t)((n0w + (lane & 15)) * 128 + (lane >> 4) * 16);

    float acc[4][4][4];
#pragma unroll
    for (int i = 0; i < 4; i++)
#pragma unroll
        for (int j = 0; j < 4; j++)
#pragma unroll
            for (int r = 0; r < 4; r++) acc[i][j][r] = 0.f;

    issue_loads(0); issue_loads(1); issue_loads(2);

    for (int c = 0; c < NCH; c++) {
        if (c < NCH - 2)      { CP_WAIT(2); }
        else if (c == NCH - 2){ CP_WAIT(1); }
        else                  { CP_WAIT(0); }
        __syncthreads();

        if (c + 3 < NCH) issue_loads(c + 3);

        const uint32_t Ast = sb + (uint32_t)(c & 3) * ASTG;
        const uint32_t Bst = sb + B_OFF + (uint32_t)(c & 3) * BSTG;

#pragma unroll
        for (int ks = 0; ks < 4; ks++) {
            uint32_t a[4][4];
#pragma unroll
            for (int i = 0; i < 4; i++) {
                uint32_t ad = Ast + SWZ(aRow + (uint32_t)(i * 2048 + ks * 32));
                LDSM4(a[i][0], a[i][1], a[i][2], a[i][3], ad);
            }
            uint32_t bf[4][2];
#pragma unroll
            for (int jj = 0; jj < 2; jj++) {
                uint32_t bd = Bst + SWZ(bRow + (uint32_t)(jj * 2048 + ks * 32));
                uint32_t r0, r1, r2, r3;
                LDSM4(r0, r1, r2, r3, bd);
                bf[2*jj][0]   = r0; bf[2*jj][1]   = r2;
                bf[2*jj+1][0] = r1; bf[2*jj+1][1] = r3;
            }
#pragma unroll
            for (int i = 0; i < 4; i++)
#pragma unroll
                for (int j = 0; j < 4; j++)
                    MMA16816(acc[i][j], a[i], bf[j]);
        }
        __syncthreads();
    }

    // ---- epilogue: bias + fast sigmoid, coalesced float2 stores ----
#pragma unroll
    for (int i = 0; i < 4; i++) {
        int row = m0 + m0w + i * 16 + (lane >> 2);
#pragma unroll
        for (int j = 0; j < 4; j++) {
            int col = n0 + n0w + j * 8 + (lane & 3) * 2;
            if (col >= N) continue;
            float bv0 = bias[col], bv1 = bias[col + 1];
            float2 v0, v1;
            v0.x = sigmoid_fast(acc[i][j][0] + bv0);
            v0.y = sigmoid_fast(acc[i][j][1] + bv1);
            v1.x = sigmoid_fast(acc[i][j][2] + bv0);
            v1.y = sigmoid_fast(acc[i][j][3] + bv1);
            *(float2*)(Z + (size_t)row * N + col)       = v0;
            *(float2*)(Z + (size_t)(row + 8) * N + col) = v1;
        }
    }
}

// ---------------------------------------------------------------------------
// Loss epilogue v3: 512 threads/row, float4 I/O on the level-3 pass.
// All logits in (0,1) -> no max shift needed for logsumexp.
// ---------------------------------------------------------------------------
__device__ __forceinline__ float blockSum512(float v, float* red) {
    int t = threadIdx.x;
#pragma unroll
    for (int off = 16; off; off >>= 1) v += __shfl_xor_sync(0xFFFFFFFFu, v, off);
    if ((t & 31) == 0) red[t >> 5] = v;
    __syncthreads();
    if (t == 0) {
        float s = 0.f;
#pragma unroll
        for (int k = 0; k < 16; k++) s += red[k];
        red[0] = s;
    }
    __syncthreads();
    float r = red[0];
    __syncthreads();
    return r;
}

__global__ __launch_bounds__(512)
void epilogue_kernel(const float* __restrict__ z1,
                     const float* __restrict__ z2,
                     const int*   __restrict__ labels,
                     float* outZ,
                     float* __restrict__ loss_rows)
{
    __shared__ float s1[N1C];
    __shared__ float s2[N2C];
    __shared__ float s3[N2C];
    __shared__ float red[16];

    const int b = blockIdx.x;
    const int t = threadIdx.x;
    const int lab  = labels[b];
    const int lab1 = lab / 100;
    const int lab2 = lab / 10;

    float* orow = outZ + (size_t)b * N3C;

    if (t < N1C) s1[t] = z1[(size_t)b * N1C + t];
    if (t < N2C) s2[t] = z2[(size_t)b * N2C + t];
    if (t < 70) {                                  // 280 floats = 70 float4
        float4 v = *(const float4*)(orow + t * 4);
        *(float4*)(s3 + t * 4) = v;
    }
    __syncthreads();

    // level 1 + level 2 partial sums
    float e1 = 0.f;
    if (t < N1C) e1 = __expf(s1[t]);
    float e2 = 0.f;
    if (t < N2C) e2 = __expf(s2[t / 10] * s2[t]);

    // level 3: fused transform + exp-sum, float4 I/O (700 groups, 512 threads)
    float e3 = 0.f;
#pragma unroll
    for (int it = 0; it < 2; it++) {
        int q = t + it * 512;
        if (q < 700) {
            int k = q * 4;
            float4 z4 = *(const float4*)(orow + k);
            float4 l4;
            l4.x = s3[(k + 0) / 100] * s3[(k + 0) / 10] * z4.x;
            l4.y = s3[(k + 1) / 100] * s3[(k + 1) / 10] * z4.y;
            l4.z = s3[(k + 2) / 100] * s3[(k + 2) / 10] * z4.z;
            l4.w = s3[(k + 3) / 100] * s3[(k + 3) / 10] * z4.w;
            *(float4*)(orow + k) = l4;
            e3 += __expf(l4.x) + __expf(l4.y) + __expf(l4.z) + __expf(l4.w);
        }
    }

    float sum1 = blockSum512(e1, red);
    float sum2 = blockSum512(e2, red);
    float sum3 = blockSum512(e3, red);   // syncthreads inside: orow writes visible

    if (t == 0) {
        float slab = orow[lab];          // transformed logit at label
        float loss1 = logf(sum1) - s1[lab1];
        float loss2 = logf(sum2) - s2[lab2 / 10] * s2[lab2];
        float loss3 = logf(sum3) - slab;
        loss_rows[b] = loss1 + loss2 + loss3;
    }
}

__global__ __launch_bounds__(1024)
void loss_reduce_kernel(const float* __restrict__ lr, float* __restrict__ dst, int B)
{
    __shared__ float red[32];
    int t = threadIdx.x;
    float s = 0.f;
    for (int i = t * 4; i < B; i += 4096) {
        float4 v = *(const float4*)(lr + i);
        s += v.x + v.y + v.z + v.w;
    }
#pragma unroll
    for (int off = 16; off; off >>= 1) s += __shfl_xor_sync(0xFFFFFFFFu, s, off);
    if ((t & 31) == 0) red[t >> 5] = s;
    __syncthreads();
    if (t == 0) {
        float tot = 0.f;
#pragma unroll
        for (int k = 0; k < 32; k++) tot += red[k];
        *dst = tot / (float)B;
    }
}

// ---------------------------------------------------------------------------
extern "C" void kernel_launch(void* const* d_in, const int* in_sizes, int n_in,
                              void* d_out, int out_size)
{
    const float* x      = (const float*)d_in[0];
    const int*   labels = (const int*)  d_in[1];
    const float* W1     = (const float*)d_in[2];
    const float* b1     = (const float*)d_in[3];
    const float* W2     = (const float*)d_in[4];
    const float* b2     = (const float*)d_in[5];
    const float* W3     = (const float*)d_in[6];
    const float* b3     = (const float*)d_in[7];

    int B = in_sizes[0] / HID;
    if (B > BMAX) B = BMAX;

    float* out = (float*)d_out;

    float *z1p, *z2p, *z3p, *lrp;
    __half *xcp, *w1p, *w2p, *w3p;
    cudaGetSymbolAddress((void**)&z1p, g_z1);
    cudaGetSymbolAddress((void**)&z2p, g_z2);
    cudaGetSymbolAddress((void**)&z3p, g_z3);
    cudaGetSymbolAddress((void**)&lrp, g_lossrows);
    cudaGetSymbolAddress((void**)&xcp, g_xc);
    cudaGetSymbolAddress((void**)&w1p, g_w1c);
    cudaGetSymbolAddress((void**)&w2p, g_w2c);
    cudaGetSymbolAddress((void**)&w3p, g_w3c);

    convert_all_kernel<<<B + N1P + N2P + N3P, 256>>>(x, W1, W2, W3, xcp, w1p, w2p, w3p, B);

    const size_t LE = (size_t)B * N3C;
    float* zdst = ((size_t)out_size >= LE) ? out : z3p;

    cudaFuncSetAttribute(gemm_mma_kernel, cudaFuncAttributeMaxDynamicSharedMemorySize, SMEM_BYTES);
    gemm_mma_kernel<<<dim3(NT_COL, B / BMt), 512, SMEM_BYTES>>>(
        xcp,
        w1p, b1, z1p,
        w2p, b2, z2p,
        w3p, b3, zdst);

    epilogue_kernel<<<B, 512>>>(z1p, z2p, labels, zdst, lrp);

    if ((size_t)out_size > LE) {
        loss_reduce_kernel<<<1, 1024>>>(lrp, out + LE, B);
    } else if ((size_t)out_size < LE && out_size >= 1) {
        loss_reduce_kernel<<<1, 1024>>>(lrp, out, B);
    }
}